// round 10
// baseline (speedup 1.0000x reference)
#include <cuda_runtime.h>
#include <cstdint>

#define TX 32
#define TY 64
#define HALO 5
#define IMG 512
#define IN_W 42                 // TX + 2*HALO
#define V_S2 43                 // u64 stride for vertical-result buffers (odd, 43%16=11)
#define NTHREADS 256
#define GRID_X 16
#define GRID_Y 8
#define GRID_Z 96
#define NBLOCKS (GRID_X * GRID_Y * GRID_Z)

#define SSIM_C1 0.0001f
#define SSIM_C2 0.0009f

// smem: two vertical-conv buffers [TY][V_S2] of packed u64
#define SMEM_U64S (2 * TY * V_S2)
#define SMEM_BYTES (SMEM_U64S * 8)   // 44,032 B -> 5 CTAs/SM

// Phase V task space: 10 chunks of 6 rows + 1 chunk of 4 rows, x IN_W columns
#define V_TASKS (11 * IN_W)          // 462 -> 2 rounds of 256, 90.2% util

typedef unsigned long long u64;

__device__ float g_partials[NBLOCKS];
__device__ unsigned int g_count = 0;

// 11-tap Gaussian, sigma=1.5, normalized
#define W0 0.00102838f
#define W1 0.00759876f
#define W2c 0.03600077f
#define W3 0.10936070f
#define W4 0.21300552f
#define W5 0.26601174f

__device__ __forceinline__ u64 pack2(float x, float y) {
    u64 r; asm("mov.b64 %0, {%1,%2};" : "=l"(r) : "f"(x), "f"(y)); return r;
}
__device__ __forceinline__ void unpack2(u64 v, float& x, float& y) {
    asm("mov.b64 {%0,%1}, %2;" : "=f"(x), "=f"(y) : "l"(v));
}
__device__ __forceinline__ u64 fma2(u64 a, u64 b, u64 c) {
    u64 d; asm("fma.rn.f32x2 %0, %1, %2, %3;" : "=l"(d) : "l"(a), "l"(b), "l"(c)); return d;
}
__device__ __forceinline__ u64 mul2(u64 a, u64 b) {
    u64 d; asm("mul.rn.f32x2 %0, %1, %2;" : "=l"(d) : "l"(a), "l"(b)); return d;
}

// Accumulator-form vertical conv chunk: H output rows at smem row R0, column x.
// Each input row loaded once, scattered into accumulators; completed outputs
// stored immediately to cap live registers at H u64-pairs.
template <int H, bool BOUND>
__device__ __forceinline__ void vchunk(
    const float* __restrict__ p1, const float* __restrict__ p2,
    u64* __restrict__ vA, u64* __restrict__ vB,
    const u64* __restrict__ w, int R0, int x, int gx, int gy0)
{
    u64 accA[H], accB[H];
    #pragma unroll
    for (int j = 0; j < H; j++) { accA[j] = 0ull; accB[j] = 0ull; }

    const int ybase = gy0 + R0;
    const bool xok = !BOUND || ((unsigned)gx < (unsigned)IMG);

    #pragma unroll
    for (int i = 0; i < H + 10; i++) {
        float a = 0.0f, b = 0.0f;
        int gy = ybase + i;
        if (!BOUND || (xok && (unsigned)gy < (unsigned)IMG)) {
            int off = gy * IMG + gx;
            a = __ldg(p1 + off);
            b = __ldg(p2 + off);
        }
        u64 sd = pack2(a + b, a - b);
        u64 sq = mul2(sd, sd);
        #pragma unroll
        for (int j = 0; j < H; j++) {
            constexpr int dummy = 0; (void)dummy;
            int k = i - j;
            if (k >= 0 && k <= 10) {
                int wk = (k <= 5) ? k : (10 - k);      // compile-time
                accA[j] = fma2(sd, w[wk], accA[j]);
                accB[j] = fma2(sq, w[wk], accB[j]);
            }
        }
        if (i >= 10) {
            int j = i - 10;
            vA[(R0 + j) * V_S2 + x] = accA[j];
            vB[(R0 + j) * V_S2 + x] = accB[j];
        }
    }
}

__global__ __launch_bounds__(NTHREADS, 5)
void ssim_main(const float* __restrict__ img1, const float* __restrict__ img2,
               float* __restrict__ out)
{
    extern __shared__ u64 smem[];
    u64* vA = smem;              // vertical conv of (s,d)     [TY][V_S2]
    u64* vB = vA + TY * V_S2;    // vertical conv of (s^2,d^2) [TY][V_S2]

    const int t = threadIdx.x;
    const int gx0 = blockIdx.x * TX - HALO;
    const int gy0 = blockIdx.y * TY - HALO;
    const size_t plane = (size_t)blockIdx.z * (IMG * IMG);
    const float* p1 = img1 + plane;
    const float* p2 = img2 + plane;

    // 6 distinct packed weights (tap symmetry)
    u64 w[6];
    w[0] = pack2(W0, W0); w[1] = pack2(W1, W1); w[2] = pack2(W2c, W2c);
    w[3] = pack2(W3, W3); w[4] = pack2(W4, W4); w[5] = pack2(W5, W5);

    const bool interior = (blockIdx.x > 0) & (blockIdx.x < GRID_X - 1) &
                          (blockIdx.y > 0) & (blockIdx.y < GRID_Y - 1);

    // ================= Phase V: accumulator-form vertical conv =================
    // 462 tasks = (10 chunks x 6 rows + 1 chunk x 4 rows) x 42 columns.
    // Warp lanes -> consecutive columns => coalesced LDG per input row.
    if (interior) {
        for (int task = t; task < V_TASKS; task += NTHREADS) {
            int cc = task / IN_W;
            int x  = task - cc * IN_W;
            int gx = gx0 + x;
            if (cc < 10) vchunk<6, false>(p1, p2, vA, vB, w, cc * 6, x, gx, gy0);
            else         vchunk<4, false>(p1, p2, vA, vB, w, 60,     x, gx, gy0);
        }
    } else {
        for (int task = t; task < V_TASKS; task += NTHREADS) {
            int cc = task / IN_W;
            int x  = task - cc * IN_W;
            int gx = gx0 + x;
            if (cc < 10) vchunk<6, true>(p1, p2, vA, vB, w, cc * 6, x, gx, gy0);
            else         vchunk<4, true>(p1, p2, vA, vB, w, 60,     x, gx, gy0);
        }
    }
    __syncthreads();

    // ================= Phase H: horizontal conv + epilogue (registers only) =========
    // 512 tasks = 8 col-chunks (4 outputs) x 64 rows = exactly 2 balanced rounds.
    // Lane -> consecutive rows; LDS.64 stride 43 => conflict-free.
    float lsum = 0.0f;
    #pragma unroll
    for (int round = 0; round < 2; round++) {
        int task = t + round * NTHREADS;
        int c = task >> 6;                // 0..7
        int r = task & 63;                // 0..63
        int ib = r * V_S2 + c * 4;

        u64 M[4], E[4];
        {
            u64 v[14];
            #pragma unroll
            for (int i = 0; i < 14; i++) v[i] = vA[ib + i];
            #pragma unroll
            for (int j = 0; j < 4; j++) M[j] = 0ull;
            #pragma unroll
            for (int k = 0; k < 11; k++) {
                int wk = (k <= 5) ? k : (10 - k);
                #pragma unroll
                for (int j = 0; j < 4; j++) M[j] = fma2(v[j + k], w[wk], M[j]);
            }
            #pragma unroll
            for (int i = 0; i < 14; i++) v[i] = vB[ib + i];
            #pragma unroll
            for (int j = 0; j < 4; j++) E[j] = 0ull;
            #pragma unroll
            for (int k = 0; k < 11; k++) {
                int wk = (k <= 5) ? k : (10 - k);
                #pragma unroll
                for (int j = 0; j < 4; j++) E[j] = fma2(v[j + k], w[wk], E[j]);
            }
        }

        #pragma unroll
        for (int o = 0; o < 4; o++) {
            float ms, md, es, ed;
            unpack2(M[o], ms, md);
            unpack2(E[o], es, ed);
            float ms2 = ms * ms, md2 = md * md;
            float mu12  = 0.25f * (ms2 - md2);              // mu1*mu2
            float musq  = 0.5f  * (ms2 + md2);              // mu1^2 + mu2^2
            float s12x2 = 0.5f  * (es - ed) - 2.0f * mu12;  // 2*sigma12
            float ssum  = 0.5f  * (es + ed) - musq;         // sigma1^2 + sigma2^2
            float num = (2.0f * mu12 + SSIM_C1) * (s12x2 + SSIM_C2);
            float den = (musq + SSIM_C1) * (ssum + SSIM_C2);
            float q = __fdividef(num, den);
            q = fminf(fmaxf(q, 0.0f), 1.0f);
            lsum += q;
        }
    }

    // ================= Block reduction =================
    #pragma unroll
    for (int off = 16; off > 0; off >>= 1)
        lsum += __shfl_down_sync(0xffffffffu, lsum, off);

    __syncthreads();   // all phase-H smem reads done; reuse smem as float scratch
    float* red = (float*)smem;
    if ((t & 31) == 0) red[t >> 5] = lsum;
    __syncthreads();

    __shared__ unsigned int s_last;
    if (t == 0) {
        float tot = 0.0f;
        #pragma unroll
        for (int wv = 0; wv < 8; wv++) tot += red[wv];
        g_partials[(blockIdx.z * GRID_Y + blockIdx.y) * GRID_X + blockIdx.x] = tot;
        __threadfence();
        unsigned int prev = atomicAdd(&g_count, 1u);
        s_last = (prev == NBLOCKS - 1);
    }
    __syncthreads();

    // ================= Last block: final reduction (deterministic order) ============
    if (s_last) {
        float acc = 0.0f;
        for (int i = t; i < NBLOCKS; i += NTHREADS)
            acc += g_partials[i];
        red[t] = acc;
        __syncthreads();
        #pragma unroll
        for (int s = NTHREADS / 2; s > 0; s >>= 1) {
            if (t < s) red[t] += red[t + s];
            __syncthreads();
        }
        if (t == 0) {
            out[0] = 1.0f - red[0] * (1.0f / (32.0f * 3.0f * 512.0f * 512.0f));
            g_count = 0;   // rearm for next graph replay
        }
    }
}

extern "C" void kernel_launch(void* const* d_in, const int* in_sizes, int n_in,
                              void* d_out, int out_size)
{
    const float* img1 = (const float*)d_in[0];
    const float* img2 = (const float*)d_in[1];

    cudaFuncSetAttribute(ssim_main,
                         cudaFuncAttributeMaxDynamicSharedMemorySize, SMEM_BYTES);

    dim3 grid(GRID_X, GRID_Y, GRID_Z);
    ssim_main<<<grid, NTHREADS, SMEM_BYTES>>>(img1, img2, (float*)d_out);
}

// round 11
// speedup vs baseline: 1.0003x; 1.0003x over previous
#include <cuda_runtime.h>
#include <cstdint>

#define TX 32
#define TY 64
#define HALO 5
#define IMG 512
#define IN_W 42                 // TX + 2*HALO
#define V_S2 43                 // u64 stride for vertical-result buffers (odd, 43%16=11)
#define NTHREADS 256
#define GRID_X 16
#define GRID_Y 8
#define GRID_Z 96
#define NBLOCKS (GRID_X * GRID_Y * GRID_Z)

#define SSIM_C1 0.0001f
#define SSIM_C2 0.0009f

// smem: two vertical-conv buffers [TY][V_S2] of packed u64
#define SMEM_U64S (2 * TY * V_S2)
#define SMEM_BYTES (SMEM_U64S * 8)   // 44,032 B -> 5 CTAs/SM

// Phase V task space: 10 chunks of 6 rows + 1 chunk of 4 rows, x IN_W columns
#define V_TASKS (11 * IN_W)          // 462 -> 2 rounds of 256, 90.2% util

typedef unsigned long long u64;

__device__ float g_partials[NBLOCKS];
__device__ unsigned int g_count = 0;

// 11-tap Gaussian, sigma=1.5, normalized
#define W0 0.00102838f
#define W1 0.00759876f
#define W2c 0.03600077f
#define W3 0.10936070f
#define W4 0.21300552f
#define W5 0.26601174f

__device__ __forceinline__ u64 pack2(float x, float y) {
    u64 r; asm("mov.b64 %0, {%1,%2};" : "=l"(r) : "f"(x), "f"(y)); return r;
}
__device__ __forceinline__ void unpack2(u64 v, float& x, float& y) {
    asm("mov.b64 {%0,%1}, %2;" : "=f"(x), "=f"(y) : "l"(v));
}
__device__ __forceinline__ u64 fma2(u64 a, u64 b, u64 c) {
    u64 d; asm("fma.rn.f32x2 %0, %1, %2, %3;" : "=l"(d) : "l"(a), "l"(b), "l"(c)); return d;
}
__device__ __forceinline__ u64 mul2(u64 a, u64 b) {
    u64 d; asm("mul.rn.f32x2 %0, %1, %2;" : "=l"(d) : "l"(a), "l"(b)); return d;
}

// Accumulator-form vertical conv chunk: H output rows at smem row R0, column x.
// Each input row loaded once, scattered into accumulators; completed outputs
// stored immediately to cap live registers at H u64-pairs.
template <int H, bool BOUND>
__device__ __forceinline__ void vchunk(
    const float* __restrict__ p1, const float* __restrict__ p2,
    u64* __restrict__ vA, u64* __restrict__ vB,
    const u64* __restrict__ w, int R0, int x, int gx, int gy0)
{
    u64 accA[H], accB[H];
    #pragma unroll
    for (int j = 0; j < H; j++) { accA[j] = 0ull; accB[j] = 0ull; }

    const int ybase = gy0 + R0;
    const bool xok = !BOUND || ((unsigned)gx < (unsigned)IMG);

    #pragma unroll
    for (int i = 0; i < H + 10; i++) {
        float a = 0.0f, b = 0.0f;
        int gy = ybase + i;
        if (!BOUND || (xok && (unsigned)gy < (unsigned)IMG)) {
            int off = gy * IMG + gx;
            a = __ldg(p1 + off);
            b = __ldg(p2 + off);
        }
        u64 sd = pack2(a + b, a - b);
        u64 sq = mul2(sd, sd);
        #pragma unroll
        for (int j = 0; j < H; j++) {
            constexpr int dummy = 0; (void)dummy;
            int k = i - j;
            if (k >= 0 && k <= 10) {
                int wk = (k <= 5) ? k : (10 - k);      // compile-time
                accA[j] = fma2(sd, w[wk], accA[j]);
                accB[j] = fma2(sq, w[wk], accB[j]);
            }
        }
        if (i >= 10) {
            int j = i - 10;
            vA[(R0 + j) * V_S2 + x] = accA[j];
            vB[(R0 + j) * V_S2 + x] = accB[j];
        }
    }
}

__global__ __launch_bounds__(NTHREADS, 5)
void ssim_main(const float* __restrict__ img1, const float* __restrict__ img2,
               float* __restrict__ out)
{
    extern __shared__ u64 smem[];
    u64* vA = smem;              // vertical conv of (s,d)     [TY][V_S2]
    u64* vB = vA + TY * V_S2;    // vertical conv of (s^2,d^2) [TY][V_S2]

    const int t = threadIdx.x;
    const int gx0 = blockIdx.x * TX - HALO;
    const int gy0 = blockIdx.y * TY - HALO;
    const size_t plane = (size_t)blockIdx.z * (IMG * IMG);
    const float* p1 = img1 + plane;
    const float* p2 = img2 + plane;

    // 6 distinct packed weights (tap symmetry)
    u64 w[6];
    w[0] = pack2(W0, W0); w[1] = pack2(W1, W1); w[2] = pack2(W2c, W2c);
    w[3] = pack2(W3, W3); w[4] = pack2(W4, W4); w[5] = pack2(W5, W5);

    const bool interior = (blockIdx.x > 0) & (blockIdx.x < GRID_X - 1) &
                          (blockIdx.y > 0) & (blockIdx.y < GRID_Y - 1);

    // ================= Phase V: accumulator-form vertical conv =================
    // 462 tasks = (10 chunks x 6 rows + 1 chunk x 4 rows) x 42 columns.
    // Warp lanes -> consecutive columns => coalesced LDG per input row.
    if (interior) {
        for (int task = t; task < V_TASKS; task += NTHREADS) {
            int cc = task / IN_W;
            int x  = task - cc * IN_W;
            int gx = gx0 + x;
            if (cc < 10) vchunk<6, false>(p1, p2, vA, vB, w, cc * 6, x, gx, gy0);
            else         vchunk<4, false>(p1, p2, vA, vB, w, 60,     x, gx, gy0);
        }
    } else {
        for (int task = t; task < V_TASKS; task += NTHREADS) {
            int cc = task / IN_W;
            int x  = task - cc * IN_W;
            int gx = gx0 + x;
            if (cc < 10) vchunk<6, true>(p1, p2, vA, vB, w, cc * 6, x, gx, gy0);
            else         vchunk<4, true>(p1, p2, vA, vB, w, 60,     x, gx, gy0);
        }
    }
    __syncthreads();

    // ================= Phase H: horizontal conv + epilogue (registers only) =========
    // 512 tasks = 8 col-chunks (4 outputs) x 64 rows = exactly 2 balanced rounds.
    // Lane -> consecutive rows; LDS.64 stride 43 => conflict-free.
    float lsum = 0.0f;
    #pragma unroll
    for (int round = 0; round < 2; round++) {
        int task = t + round * NTHREADS;
        int c = task >> 6;                // 0..7
        int r = task & 63;                // 0..63
        int ib = r * V_S2 + c * 4;

        u64 M[4], E[4];
        {
            u64 v[14];
            #pragma unroll
            for (int i = 0; i < 14; i++) v[i] = vA[ib + i];
            #pragma unroll
            for (int j = 0; j < 4; j++) M[j] = 0ull;
            #pragma unroll
            for (int k = 0; k < 11; k++) {
                int wk = (k <= 5) ? k : (10 - k);
                #pragma unroll
                for (int j = 0; j < 4; j++) M[j] = fma2(v[j + k], w[wk], M[j]);
            }
            #pragma unroll
            for (int i = 0; i < 14; i++) v[i] = vB[ib + i];
            #pragma unroll
            for (int j = 0; j < 4; j++) E[j] = 0ull;
            #pragma unroll
            for (int k = 0; k < 11; k++) {
                int wk = (k <= 5) ? k : (10 - k);
                #pragma unroll
                for (int j = 0; j < 4; j++) E[j] = fma2(v[j + k], w[wk], E[j]);
            }
        }

        #pragma unroll
        for (int o = 0; o < 4; o++) {
            float ms, md, es, ed;
            unpack2(M[o], ms, md);
            unpack2(E[o], es, ed);
            float ms2 = ms * ms, md2 = md * md;
            float mu12  = 0.25f * (ms2 - md2);              // mu1*mu2
            float musq  = 0.5f  * (ms2 + md2);              // mu1^2 + mu2^2
            float s12x2 = 0.5f  * (es - ed) - 2.0f * mu12;  // 2*sigma12
            float ssum  = 0.5f  * (es + ed) - musq;         // sigma1^2 + sigma2^2
            float num = (2.0f * mu12 + SSIM_C1) * (s12x2 + SSIM_C2);
            float den = (musq + SSIM_C1) * (ssum + SSIM_C2);
            float q = __fdividef(num, den);
            q = fminf(fmaxf(q, 0.0f), 1.0f);
            lsum += q;
        }
    }

    // ================= Block reduction =================
    #pragma unroll
    for (int off = 16; off > 0; off >>= 1)
        lsum += __shfl_down_sync(0xffffffffu, lsum, off);

    __syncthreads();   // all phase-H smem reads done; reuse smem as float scratch
    float* red = (float*)smem;
    if ((t & 31) == 0) red[t >> 5] = lsum;
    __syncthreads();

    __shared__ unsigned int s_last;
    if (t == 0) {
        float tot = 0.0f;
        #pragma unroll
        for (int wv = 0; wv < 8; wv++) tot += red[wv];
        g_partials[(blockIdx.z * GRID_Y + blockIdx.y) * GRID_X + blockIdx.x] = tot;
        __threadfence();
        unsigned int prev = atomicAdd(&g_count, 1u);
        s_last = (prev == NBLOCKS - 1);
    }
    __syncthreads();

    // ================= Last block: final reduction (deterministic order) ============
    if (s_last) {
        float acc = 0.0f;
        for (int i = t; i < NBLOCKS; i += NTHREADS)
            acc += g_partials[i];
        red[t] = acc;
        __syncthreads();
        #pragma unroll
        for (int s = NTHREADS / 2; s > 0; s >>= 1) {
            if (t < s) red[t] += red[t + s];
            __syncthreads();
        }
        if (t == 0) {
            out[0] = 1.0f - red[0] * (1.0f / (32.0f * 3.0f * 512.0f * 512.0f));
            g_count = 0;   // rearm for next graph replay
        }
    }
}

extern "C" void kernel_launch(void* const* d_in, const int* in_sizes, int n_in,
                              void* d_out, int out_size)
{
    const float* img1 = (const float*)d_in[0];
    const float* img2 = (const float*)d_in[1];

    cudaFuncSetAttribute(ssim_main,
                         cudaFuncAttributeMaxDynamicSharedMemorySize, SMEM_BYTES);

    dim3 grid(GRID_X, GRID_Y, GRID_Z);
    ssim_main<<<grid, NTHREADS, SMEM_BYTES>>>(img1, img2, (float*)d_out);
}

// round 12
// speedup vs baseline: 1.0079x; 1.0076x over previous
#include <cuda_runtime.h>
#include <cstdint>

#define TX 32
#define TY 64
#define HALO 5
#define IMG 512
#define IN_W 42                 // TX + 2*HALO
#define V_S2 43                 // u64 stride for vertical-result buffers (odd, 43%16=11)
#define NTHREADS 256
#define GRID_X 16
#define GRID_Y 8
#define GRID_Z 96
#define NBLOCKS (GRID_X * GRID_Y * GRID_Z)

#define SSIM_C1 0.0001f
#define SSIM_C2 0.0009f

// smem: two vertical-conv buffers [TY][V_S2] of packed u64
#define SMEM_U64S (2 * TY * V_S2)
#define SMEM_BYTES (SMEM_U64S * 8)   // 44,032 B -> 5 CTAs/SM

// Phase V task space: 10 chunks of 6 rows + 1 chunk of 4 rows, x IN_W columns
#define V_TASKS (11 * IN_W)          // 462 -> 2 rounds of 256, 90.2% util

typedef unsigned long long u64;

__device__ float g_partials[NBLOCKS];
__device__ unsigned int g_count = 0;

// 11-tap Gaussian, sigma=1.5, normalized
#define W0 0.00102838f
#define W1 0.00759876f
#define W2c 0.03600077f
#define W3 0.10936070f
#define W4 0.21300552f
#define W5 0.26601174f

__device__ __forceinline__ u64 pack2(float x, float y) {
    u64 r; asm("mov.b64 %0, {%1,%2};" : "=l"(r) : "f"(x), "f"(y)); return r;
}
__device__ __forceinline__ void unpack2(u64 v, float& x, float& y) {
    asm("mov.b64 {%0,%1}, %2;" : "=f"(x), "=f"(y) : "l"(v));
}
__device__ __forceinline__ u64 fma2(u64 a, u64 b, u64 c) {
    u64 d; asm("fma.rn.f32x2 %0, %1, %2, %3;" : "=l"(d) : "l"(a), "l"(b), "l"(c)); return d;
}
__device__ __forceinline__ u64 mul2(u64 a, u64 b) {
    u64 d; asm("mul.rn.f32x2 %0, %1, %2;" : "=l"(d) : "l"(a), "l"(b)); return d;
}

// Accumulator-form vertical conv chunk: H output rows at smem row R0, column x.
// Each input row loaded once, scattered into accumulators; completed outputs
// stored immediately to cap live registers at H u64-pairs.
template <int H, bool BOUND>
__device__ __forceinline__ void vchunk(
    const float* __restrict__ p1, const float* __restrict__ p2,
    u64* __restrict__ vA, u64* __restrict__ vB,
    const u64* __restrict__ w, int R0, int x, int gx, int gy0)
{
    u64 accA[H], accB[H];
    #pragma unroll
    for (int j = 0; j < H; j++) { accA[j] = 0ull; accB[j] = 0ull; }

    const int ybase = gy0 + R0;
    const bool xok = !BOUND || ((unsigned)gx < (unsigned)IMG);

    #pragma unroll
    for (int i = 0; i < H + 10; i++) {
        float a = 0.0f, b = 0.0f;
        int gy = ybase + i;
        if (!BOUND || (xok && (unsigned)gy < (unsigned)IMG)) {
            int off = gy * IMG + gx;
            a = __ldg(p1 + off);
            b = __ldg(p2 + off);
        }
        u64 sd = pack2(a + b, a - b);
        u64 sq = mul2(sd, sd);
        #pragma unroll
        for (int j = 0; j < H; j++) {
            constexpr int dummy = 0; (void)dummy;
            int k = i - j;
            if (k >= 0 && k <= 10) {
                int wk = (k <= 5) ? k : (10 - k);      // compile-time
                accA[j] = fma2(sd, w[wk], accA[j]);
                accB[j] = fma2(sq, w[wk], accB[j]);
            }
        }
        if (i >= 10) {
            int j = i - 10;
            vA[(R0 + j) * V_S2 + x] = accA[j];
            vB[(R0 + j) * V_S2 + x] = accB[j];
        }
    }
}

__global__ __launch_bounds__(NTHREADS, 5)
void ssim_main(const float* __restrict__ img1, const float* __restrict__ img2,
               float* __restrict__ out)
{
    extern __shared__ u64 smem[];
    u64* vA = smem;              // vertical conv of (s,d)     [TY][V_S2]
    u64* vB = vA + TY * V_S2;    // vertical conv of (s^2,d^2) [TY][V_S2]

    const int t = threadIdx.x;
    const int gx0 = blockIdx.x * TX - HALO;
    const int gy0 = blockIdx.y * TY - HALO;
    const size_t plane = (size_t)blockIdx.z * (IMG * IMG);
    const float* p1 = img1 + plane;
    const float* p2 = img2 + plane;

    // 6 distinct packed weights (tap symmetry)
    u64 w[6];
    w[0] = pack2(W0, W0); w[1] = pack2(W1, W1); w[2] = pack2(W2c, W2c);
    w[3] = pack2(W3, W3); w[4] = pack2(W4, W4); w[5] = pack2(W5, W5);

    const bool interior = (blockIdx.x > 0) & (blockIdx.x < GRID_X - 1) &
                          (blockIdx.y > 0) & (blockIdx.y < GRID_Y - 1);

    // ================= Phase V: accumulator-form vertical conv =================
    // 462 tasks = (10 chunks x 6 rows + 1 chunk x 4 rows) x 42 columns.
    // Warp lanes -> consecutive columns => coalesced LDG per input row.
    if (interior) {
        for (int task = t; task < V_TASKS; task += NTHREADS) {
            int cc = task / IN_W;
            int x  = task - cc * IN_W;
            int gx = gx0 + x;
            if (cc < 10) vchunk<6, false>(p1, p2, vA, vB, w, cc * 6, x, gx, gy0);
            else         vchunk<4, false>(p1, p2, vA, vB, w, 60,     x, gx, gy0);
        }
    } else {
        for (int task = t; task < V_TASKS; task += NTHREADS) {
            int cc = task / IN_W;
            int x  = task - cc * IN_W;
            int gx = gx0 + x;
            if (cc < 10) vchunk<6, true>(p1, p2, vA, vB, w, cc * 6, x, gx, gy0);
            else         vchunk<4, true>(p1, p2, vA, vB, w, 60,     x, gx, gy0);
        }
    }
    __syncthreads();

    // ================= Phase H: horizontal conv + epilogue (registers only) =========
    // 512 tasks = 8 col-chunks (4 outputs) x 64 rows = exactly 2 balanced rounds.
    // Lane -> consecutive rows; LDS.64 stride 43 => conflict-free.
    float lsum = 0.0f;
    #pragma unroll
    for (int round = 0; round < 2; round++) {
        int task = t + round * NTHREADS;
        int c = task >> 6;                // 0..7
        int r = task & 63;                // 0..63
        int ib = r * V_S2 + c * 4;

        u64 M[4], E[4];
        {
            u64 v[14];
            #pragma unroll
            for (int i = 0; i < 14; i++) v[i] = vA[ib + i];
            #pragma unroll
            for (int j = 0; j < 4; j++) M[j] = 0ull;
            #pragma unroll
            for (int k = 0; k < 11; k++) {
                int wk = (k <= 5) ? k : (10 - k);
                #pragma unroll
                for (int j = 0; j < 4; j++) M[j] = fma2(v[j + k], w[wk], M[j]);
            }
            #pragma unroll
            for (int i = 0; i < 14; i++) v[i] = vB[ib + i];
            #pragma unroll
            for (int j = 0; j < 4; j++) E[j] = 0ull;
            #pragma unroll
            for (int k = 0; k < 11; k++) {
                int wk = (k <= 5) ? k : (10 - k);
                #pragma unroll
                for (int j = 0; j < 4; j++) E[j] = fma2(v[j + k], w[wk], E[j]);
            }
        }

        #pragma unroll
        for (int o = 0; o < 4; o++) {
            float ms, md, es, ed;
            unpack2(M[o], ms, md);
            unpack2(E[o], es, ed);
            float ms2 = ms * ms, md2 = md * md;
            float mu12  = 0.25f * (ms2 - md2);              // mu1*mu2
            float musq  = 0.5f  * (ms2 + md2);              // mu1^2 + mu2^2
            float s12x2 = 0.5f  * (es - ed) - 2.0f * mu12;  // 2*sigma12
            float ssum  = 0.5f  * (es + ed) - musq;         // sigma1^2 + sigma2^2
            float num = (2.0f * mu12 + SSIM_C1) * (s12x2 + SSIM_C2);
            float den = (musq + SSIM_C1) * (ssum + SSIM_C2);
            float q = __fdividef(num, den);
            q = fminf(fmaxf(q, 0.0f), 1.0f);
            lsum += q;
        }
    }

    // ================= Block reduction =================
    #pragma unroll
    for (int off = 16; off > 0; off >>= 1)
        lsum += __shfl_down_sync(0xffffffffu, lsum, off);

    __syncthreads();   // all phase-H smem reads done; reuse smem as float scratch
    float* red = (float*)smem;
    if ((t & 31) == 0) red[t >> 5] = lsum;
    __syncthreads();

    __shared__ unsigned int s_last;
    if (t == 0) {
        float tot = 0.0f;
        #pragma unroll
        for (int wv = 0; wv < 8; wv++) tot += red[wv];
        g_partials[(blockIdx.z * GRID_Y + blockIdx.y) * GRID_X + blockIdx.x] = tot;
        __threadfence();
        unsigned int prev = atomicAdd(&g_count, 1u);
        s_last = (prev == NBLOCKS - 1);
    }
    __syncthreads();

    // ================= Last block: final reduction (deterministic order) ============
    if (s_last) {
        float acc = 0.0f;
        for (int i = t; i < NBLOCKS; i += NTHREADS)
            acc += g_partials[i];
        red[t] = acc;
        __syncthreads();
        #pragma unroll
        for (int s = NTHREADS / 2; s > 0; s >>= 1) {
            if (t < s) red[t] += red[t + s];
            __syncthreads();
        }
        if (t == 0) {
            out[0] = 1.0f - red[0] * (1.0f / (32.0f * 3.0f * 512.0f * 512.0f));
            g_count = 0;   // rearm for next graph replay
        }
    }
}

extern "C" void kernel_launch(void* const* d_in, const int* in_sizes, int n_in,
                              void* d_out, int out_size)
{
    const float* img1 = (const float*)d_in[0];
    const float* img2 = (const float*)d_in[1];

    cudaFuncSetAttribute(ssim_main,
                         cudaFuncAttributeMaxDynamicSharedMemorySize, SMEM_BYTES);

    dim3 grid(GRID_X, GRID_Y, GRID_Z);
    ssim_main<<<grid, NTHREADS, SMEM_BYTES>>>(img1, img2, (float*)d_out);
}

// round 13
// speedup vs baseline: 1.0101x; 1.0021x over previous
#include <cuda_runtime.h>
#include <cstdint>

#define TX 32
#define TY 64
#define HALO 5
#define IMG 512
#define IN_W 42                 // TX + 2*HALO
#define V_S2 43                 // u64 stride for vertical-result buffers (odd, 43%16=11)
#define NTHREADS 256
#define GRID_X 16
#define GRID_Y 8
#define GRID_Z 96
#define NBLOCKS (GRID_X * GRID_Y * GRID_Z)

#define SSIM_C1 0.0001f
#define SSIM_C2 0.0009f

// smem: two vertical-conv buffers [TY][V_S2] of packed u64
#define SMEM_U64S (2 * TY * V_S2)
#define SMEM_BYTES (SMEM_U64S * 8)   // 44,032 B -> 5 CTAs/SM

// Phase V task space: 10 chunks of 6 rows + 1 chunk of 4 rows, x IN_W columns
#define V_TASKS (11 * IN_W)          // 462 -> 2 rounds of 256, 90.2% util

typedef unsigned long long u64;

__device__ float g_partials[NBLOCKS];
__device__ unsigned int g_count = 0;

// 11-tap Gaussian, sigma=1.5, normalized
#define W0 0.00102838f
#define W1 0.00759876f
#define W2c 0.03600077f
#define W3 0.10936070f
#define W4 0.21300552f
#define W5 0.26601174f

__device__ __forceinline__ u64 pack2(float x, float y) {
    u64 r; asm("mov.b64 %0, {%1,%2};" : "=l"(r) : "f"(x), "f"(y)); return r;
}
__device__ __forceinline__ void unpack2(u64 v, float& x, float& y) {
    asm("mov.b64 {%0,%1}, %2;" : "=f"(x), "=f"(y) : "l"(v));
}
__device__ __forceinline__ u64 fma2(u64 a, u64 b, u64 c) {
    u64 d; asm("fma.rn.f32x2 %0, %1, %2, %3;" : "=l"(d) : "l"(a), "l"(b), "l"(c)); return d;
}
__device__ __forceinline__ u64 mul2(u64 a, u64 b) {
    u64 d; asm("mul.rn.f32x2 %0, %1, %2;" : "=l"(d) : "l"(a), "l"(b)); return d;
}

// Accumulator-form vertical conv chunk: H output rows at smem row R0, column x.
// Each input row loaded once, scattered into accumulators; completed outputs
// stored immediately to cap live registers at H u64-pairs.
template <int H, bool BOUND>
__device__ __forceinline__ void vchunk(
    const float* __restrict__ p1, const float* __restrict__ p2,
    u64* __restrict__ vA, u64* __restrict__ vB,
    const u64* __restrict__ w, int R0, int x, int gx, int gy0)
{
    u64 accA[H], accB[H];
    #pragma unroll
    for (int j = 0; j < H; j++) { accA[j] = 0ull; accB[j] = 0ull; }

    const int ybase = gy0 + R0;
    const bool xok = !BOUND || ((unsigned)gx < (unsigned)IMG);

    #pragma unroll
    for (int i = 0; i < H + 10; i++) {
        float a = 0.0f, b = 0.0f;
        int gy = ybase + i;
        if (!BOUND || (xok && (unsigned)gy < (unsigned)IMG)) {
            int off = gy * IMG + gx;
            a = __ldg(p1 + off);
            b = __ldg(p2 + off);
        }
        u64 sd = pack2(a + b, a - b);
        u64 sq = mul2(sd, sd);
        #pragma unroll
        for (int j = 0; j < H; j++) {
            constexpr int dummy = 0; (void)dummy;
            int k = i - j;
            if (k >= 0 && k <= 10) {
                int wk = (k <= 5) ? k : (10 - k);      // compile-time
                accA[j] = fma2(sd, w[wk], accA[j]);
                accB[j] = fma2(sq, w[wk], accB[j]);
            }
        }
        if (i >= 10) {
            int j = i - 10;
            vA[(R0 + j) * V_S2 + x] = accA[j];
            vB[(R0 + j) * V_S2 + x] = accB[j];
        }
    }
}

__global__ __launch_bounds__(NTHREADS, 5)
void ssim_main(const float* __restrict__ img1, const float* __restrict__ img2,
               float* __restrict__ out)
{
    extern __shared__ u64 smem[];
    u64* vA = smem;              // vertical conv of (s,d)     [TY][V_S2]
    u64* vB = vA + TY * V_S2;    // vertical conv of (s^2,d^2) [TY][V_S2]

    const int t = threadIdx.x;
    const int gx0 = blockIdx.x * TX - HALO;
    const int gy0 = blockIdx.y * TY - HALO;
    const size_t plane = (size_t)blockIdx.z * (IMG * IMG);
    const float* p1 = img1 + plane;
    const float* p2 = img2 + plane;

    // 6 distinct packed weights (tap symmetry)
    u64 w[6];
    w[0] = pack2(W0, W0); w[1] = pack2(W1, W1); w[2] = pack2(W2c, W2c);
    w[3] = pack2(W3, W3); w[4] = pack2(W4, W4); w[5] = pack2(W5, W5);

    const bool interior = (blockIdx.x > 0) & (blockIdx.x < GRID_X - 1) &
                          (blockIdx.y > 0) & (blockIdx.y < GRID_Y - 1);

    // ================= Phase V: accumulator-form vertical conv =================
    // 462 tasks = (10 chunks x 6 rows + 1 chunk x 4 rows) x 42 columns.
    // Warp lanes -> consecutive columns => coalesced LDG per input row.
    if (interior) {
        for (int task = t; task < V_TASKS; task += NTHREADS) {
            int cc = task / IN_W;
            int x  = task - cc * IN_W;
            int gx = gx0 + x;
            if (cc < 10) vchunk<6, false>(p1, p2, vA, vB, w, cc * 6, x, gx, gy0);
            else         vchunk<4, false>(p1, p2, vA, vB, w, 60,     x, gx, gy0);
        }
    } else {
        for (int task = t; task < V_TASKS; task += NTHREADS) {
            int cc = task / IN_W;
            int x  = task - cc * IN_W;
            int gx = gx0 + x;
            if (cc < 10) vchunk<6, true>(p1, p2, vA, vB, w, cc * 6, x, gx, gy0);
            else         vchunk<4, true>(p1, p2, vA, vB, w, 60,     x, gx, gy0);
        }
    }
    __syncthreads();

    // ================= Phase H: horizontal conv + epilogue (registers only) =========
    // 512 tasks = 8 col-chunks (4 outputs) x 64 rows = exactly 2 balanced rounds.
    // Lane -> consecutive rows; LDS.64 stride 43 => conflict-free.
    float lsum = 0.0f;
    #pragma unroll
    for (int round = 0; round < 2; round++) {
        int task = t + round * NTHREADS;
        int c = task >> 6;                // 0..7
        int r = task & 63;                // 0..63
        int ib = r * V_S2 + c * 4;

        u64 M[4], E[4];
        {
            u64 v[14];
            #pragma unroll
            for (int i = 0; i < 14; i++) v[i] = vA[ib + i];
            #pragma unroll
            for (int j = 0; j < 4; j++) M[j] = 0ull;
            #pragma unroll
            for (int k = 0; k < 11; k++) {
                int wk = (k <= 5) ? k : (10 - k);
                #pragma unroll
                for (int j = 0; j < 4; j++) M[j] = fma2(v[j + k], w[wk], M[j]);
            }
            #pragma unroll
            for (int i = 0; i < 14; i++) v[i] = vB[ib + i];
            #pragma unroll
            for (int j = 0; j < 4; j++) E[j] = 0ull;
            #pragma unroll
            for (int k = 0; k < 11; k++) {
                int wk = (k <= 5) ? k : (10 - k);
                #pragma unroll
                for (int j = 0; j < 4; j++) E[j] = fma2(v[j + k], w[wk], E[j]);
            }
        }

        #pragma unroll
        for (int o = 0; o < 4; o++) {
            float ms, md, es, ed;
            unpack2(M[o], ms, md);
            unpack2(E[o], es, ed);
            float ms2 = ms * ms, md2 = md * md;
            float mu12  = 0.25f * (ms2 - md2);              // mu1*mu2
            float musq  = 0.5f  * (ms2 + md2);              // mu1^2 + mu2^2
            float s12x2 = 0.5f  * (es - ed) - 2.0f * mu12;  // 2*sigma12
            float ssum  = 0.5f  * (es + ed) - musq;         // sigma1^2 + sigma2^2
            float num = (2.0f * mu12 + SSIM_C1) * (s12x2 + SSIM_C2);
            float den = (musq + SSIM_C1) * (ssum + SSIM_C2);
            float q = __fdividef(num, den);
            q = fminf(fmaxf(q, 0.0f), 1.0f);
            lsum += q;
        }
    }

    // ================= Block reduction =================
    #pragma unroll
    for (int off = 16; off > 0; off >>= 1)
        lsum += __shfl_down_sync(0xffffffffu, lsum, off);

    __syncthreads();   // all phase-H smem reads done; reuse smem as float scratch
    float* red = (float*)smem;
    if ((t & 31) == 0) red[t >> 5] = lsum;
    __syncthreads();

    __shared__ unsigned int s_last;
    if (t == 0) {
        float tot = 0.0f;
        #pragma unroll
        for (int wv = 0; wv < 8; wv++) tot += red[wv];
        g_partials[(blockIdx.z * GRID_Y + blockIdx.y) * GRID_X + blockIdx.x] = tot;
        __threadfence();
        unsigned int prev = atomicAdd(&g_count, 1u);
        s_last = (prev == NBLOCKS - 1);
    }
    __syncthreads();

    // ================= Last block: final reduction (deterministic order) ============
    if (s_last) {
        float acc = 0.0f;
        for (int i = t; i < NBLOCKS; i += NTHREADS)
            acc += g_partials[i];
        red[t] = acc;
        __syncthreads();
        #pragma unroll
        for (int s = NTHREADS / 2; s > 0; s >>= 1) {
            if (t < s) red[t] += red[t + s];
            __syncthreads();
        }
        if (t == 0) {
            out[0] = 1.0f - red[0] * (1.0f / (32.0f * 3.0f * 512.0f * 512.0f));
            g_count = 0;   // rearm for next graph replay
        }
    }
}

extern "C" void kernel_launch(void* const* d_in, const int* in_sizes, int n_in,
                              void* d_out, int out_size)
{
    const float* img1 = (const float*)d_in[0];
    const float* img2 = (const float*)d_in[1];

    cudaFuncSetAttribute(ssim_main,
                         cudaFuncAttributeMaxDynamicSharedMemorySize, SMEM_BYTES);

    dim3 grid(GRID_X, GRID_Y, GRID_Z);
    ssim_main<<<grid, NTHREADS, SMEM_BYTES>>>(img1, img2, (float*)d_out);
}